// round 6
// baseline (speedup 1.0000x reference)
#include <cuda_runtime.h>

#define T_ 8
#define B_ 4
#define C_ 128
#define HW_ 9216      // 96*96
#define HW4_ 2304     // HW_/4
#define NMAP 36       // T*B + B maps to resize
#define NTB 32        // T*B
#define NP1 288       // pass1 partials per tb: 18 px-tiles * 16 c-chunks
#define NPV 18        // vsum partials per tb

// scratch (static __device__ — no allocation)
__device__ float g_tv[B_ * HW_];
__device__ float g_rv[NTB * HW_];
__device__ float g_pgs[NTB * NP1];
__device__ float g_pvs[NTB * NPV];
__device__ float g_gs[NTB];

// ---------------------------------------------------------------------------
// 1) antialiased (jax-style) 384->96 resize + threshold > 0.5
// ---------------------------------------------------------------------------
__global__ void resize_kernel(const float* __restrict__ tvmap,
                              const float* __restrict__ rvmaps) {
    int idx = blockIdx.x * blockDim.x + threadIdx.x;
    if (idx >= NMAP * HW_) return;
    int m = idx / HW_;
    int p = idx - m * HW_;
    int oy = p / 96, ox = p - oy * 96;

    const float* src = (m < B_) ? (tvmap + (size_t)m * 147456)
                                : (rvmaps + (size_t)(m - B_) * 147456);

    const float wtab[8] = {1.f, 3.f, 5.f, 7.f, 7.f, 5.f, 3.f, 1.f};
    int iy0 = 4 * oy - 2, ix0 = 4 * ox - 2;

    float wx[8];
    float wxs = 0.f;
#pragma unroll
    for (int k = 0; k < 8; k++) {
        int ix = ix0 + k;
        wx[k] = (ix >= 0 && ix < 384) ? wtab[k] : 0.f;
        wxs += wx[k];
    }

    float acc = 0.f, wys = 0.f;
#pragma unroll
    for (int ky = 0; ky < 8; ky++) {
        int iy = iy0 + ky;
        if (iy < 0 || iy >= 384) continue;
        wys += wtab[ky];
        const float* row = src + iy * 384;
        float ra = 0.f;
#pragma unroll
        for (int kx = 0; kx < 8; kx++) {
            if (wx[kx] != 0.f) ra += wx[kx] * row[ix0 + kx];
        }
        acc += wtab[ky] * ra;
    }
    float val = acc / (wys * wxs);
    float bin = (val > 0.5f) ? 1.f : 0.f;
    if (m < B_) g_tv[m * HW_ + p] = bin;
    else        g_rv[(m - B_) * HW_ + p] = bin;
}

// ---------------------------------------------------------------------------
// 2) masked correlation partials with SPARSE r_feat loads (skip mask==0).
//    grid = (18 px-tiles, 16 c-chunks of 8, 4 b), 128 thr
// ---------------------------------------------------------------------------
__global__ void __launch_bounds__(128) pass1_kernel(const float* __restrict__ values,
                                                    float* __restrict__ d_out) {
    int b = blockIdx.z;
    int chunk = blockIdx.y;
    int c0 = chunk * 8;
    int i4 = blockIdx.x * 128 + threadIdx.x;   // 0..2303

    const float4* tf = (const float4*)values + ((size_t)b * C_ + c0) * HW4_ + i4;
    const float4* rf = (const float4*)values + ((size_t)(B_ + b) * C_ + c0) * HW4_ + i4;
    float4* outp = (float4*)d_out + ((size_t)b * 257 + c0) * HW4_ + i4;
    const size_t tstride = (size_t)B_ * C_ * HW4_;

    // per-lane liveness bitmask over t (exact: skipped terms are multiplied by 0)
    float4 tv = ((const float4*)g_tv)[b * HW4_ + i4];
    unsigned live = 0;
#pragma unroll
    for (int t = 0; t < T_; t++) {
        float4 rv = __ldg((const float4*)g_rv + (t * B_ + b) * HW4_ + i4);
        float s = tv.x * rv.x + tv.y * rv.y + tv.z * rv.z + tv.w * rv.w;
        if (s > 0.f) live |= (1u << t);
    }

    float4 acc[T_];
#pragma unroll
    for (int t = 0; t < T_; t++) acc[t] = make_float4(0.f, 0.f, 0.f, 0.f);

#pragma unroll 2
    for (int c = 0; c < 8; c++) {
        float4 a = __ldg(tf + c * HW4_);
        outp[c * HW4_] = a;   // t_feat -> out ch 0..127 (each element exactly once)
#pragma unroll
        for (int t = 0; t < T_; t++) {
            if (live & (1u << t)) {
                float4 r = __ldcs(rf + t * tstride + c * HW4_);
                acc[t].x += a.x * r.x; acc[t].y += a.y * r.y;
                acc[t].z += a.z * r.z; acc[t].w += a.w * r.w;
            }
        }
    }

    float lg[T_], lv[T_];
#pragma unroll
    for (int t = 0; t < T_; t++) {
        float4 rv = __ldg((const float4*)g_rv + (t * B_ + b) * HW4_ + i4);
        float m0 = tv.x * rv.x, m1 = tv.y * rv.y, m2 = tv.z * rv.z, m3 = tv.w * rv.w;
        lg[t] = acc[t].x * m0 + acc[t].y * m1 + acc[t].z * m2 + acc[t].w * m3;
        lv[t] = m0 + m1 + m2 + m3;
    }

#pragma unroll
    for (int o = 16; o > 0; o >>= 1) {
#pragma unroll
        for (int t = 0; t < T_; t++)
            lg[t] += __shfl_down_sync(0xffffffffu, lg[t], o);
    }
    if (chunk == 0) {
#pragma unroll
        for (int o = 16; o > 0; o >>= 1) {
#pragma unroll
            for (int t = 0; t < T_; t++)
                lv[t] += __shfl_down_sync(0xffffffffu, lv[t], o);
        }
    }

    __shared__ float sg[4][T_], sv[4][T_];
    int lane = threadIdx.x & 31, w = threadIdx.x >> 5;
    if (lane == 0) {
#pragma unroll
        for (int t = 0; t < T_; t++) { sg[w][t] = lg[t]; sv[w][t] = lv[t]; }
    }
    __syncthreads();
    if (threadIdx.x < T_) {
        int t = threadIdx.x;
        float a = 0.f, v = 0.f;
#pragma unroll
        for (int i = 0; i < 4; i++) { a += sg[i][t]; v += sv[i][t]; }
        g_pgs[(t * B_ + b) * NP1 + blockIdx.x * 16 + chunk] = a;
        if (chunk == 0) g_pvs[(t * B_ + b) * NPV + blockIdx.x] = v;
    }
}

// ---------------------------------------------------------------------------
// 3) finalize gs: 256 threads, 8 lanes per tb reduce 288 partials
// ---------------------------------------------------------------------------
__global__ void __launch_bounds__(256) finalize_kernel(float* __restrict__ d_out) {
    int tb = threadIdx.x >> 3;
    int j = threadIdx.x & 7;
    float gsum = 0.f;
#pragma unroll
    for (int k = 0; k < NP1 / 8; k++) gsum += g_pgs[tb * NP1 + j + 8 * k];
#pragma unroll
    for (int o = 4; o > 0; o >>= 1)
        gsum += __shfl_down_sync(0xffffffffu, gsum, o, 8);
    if (j == 0) {
        float vsum = 0.f;
#pragma unroll
        for (int i = 0; i < NPV; i++) vsum += g_pvs[tb * NPV + i];
        float g = (vsum < 1e-4f) ? 0.f : (gsum / vsum) * (1.f / 128.f);
        g_gs[tb] = g;
        d_out[(size_t)B_ * 257 * HW_ + (size_t)B_ * HW_ + tb] = g;
    }
}

// ---------------------------------------------------------------------------
// 4) fused softmax + c_out + c_mask with SPARSE r_feat loads (skip rv==0).
//    grid = (9 px-tiles, 32 c-chunks of 4, 4 b)
// ---------------------------------------------------------------------------
__global__ void __launch_bounds__(256) pass2_kernel(const float* __restrict__ values,
                                                    float* __restrict__ d_out) {
    int i4 = blockIdx.x * 256 + threadIdx.x;   // 0..2303
    int c0 = blockIdx.y * 4;
    int b = blockIdx.z;

    __shared__ float sgs[T_];
    if (threadIdx.x < T_) sgs[threadIdx.x] = g_gs[threadIdx.x * B_ + b];
    __syncthreads();

    // load rv, build live mask, softmax in place (rv binary)
    float4 cm[T_];
    unsigned live = 0;
#pragma unroll
    for (int t = 0; t < T_; t++) {
        cm[t] = __ldg((const float4*)g_rv + (t * B_ + b) * HW4_ + i4);
        if (cm[t].x + cm[t].y + cm[t].z + cm[t].w > 0.f) live |= (1u << t);
    }

    float4 mx = make_float4(-1e30f, -1e30f, -1e30f, -1e30f);
#pragma unroll
    for (int t = 0; t < T_; t++) {
        float g = sgs[t];
        mx.x = fmaxf(mx.x, g * cm[t].x); mx.y = fmaxf(mx.y, g * cm[t].y);
        mx.z = fmaxf(mx.z, g * cm[t].z); mx.w = fmaxf(mx.w, g * cm[t].w);
    }
    float4 ms = make_float4(0.f, 0.f, 0.f, 0.f);
#pragma unroll
    for (int t = 0; t < T_; t++) {
        float g = sgs[t];
        float ex = __expf(g * cm[t].x - mx.x) * cm[t].x;
        float ey = __expf(g * cm[t].y - mx.y) * cm[t].y;
        float ez = __expf(g * cm[t].z - mx.z) * cm[t].z;
        float ew = __expf(g * cm[t].w - mx.w) * cm[t].w;
        cm[t] = make_float4(ex, ey, ez, ew);
        ms.x += ex; ms.y += ey; ms.z += ez; ms.w += ew;
    }
    float4 inv;
    inv.x = 1.f / (ms.x + ((ms.x < 1e-4f) ? 1.f : 0.f));
    inv.y = 1.f / (ms.y + ((ms.y < 1e-4f) ? 1.f : 0.f));
    inv.z = 1.f / (ms.z + ((ms.z < 1e-4f) ? 1.f : 0.f));
    inv.w = 1.f / (ms.w + ((ms.w < 1e-4f) ? 1.f : 0.f));
#pragma unroll
    for (int t = 0; t < T_; t++) {
        cm[t].x *= inv.x; cm[t].y *= inv.y; cm[t].z *= inv.z; cm[t].w *= inv.w;
    }

    if (blockIdx.y == 0) {   // c_mask = 1 - ms/msd, written once per pixel
        float4 msk = make_float4(1.f - ms.x * inv.x, 1.f - ms.y * inv.y,
                                 1.f - ms.z * inv.z, 1.f - ms.w * inv.w);
        float4* op = (float4*)d_out;
        op[((size_t)b * 257 + 256) * HW4_ + i4] = msk;
        op[(size_t)B_ * 257 * HW4_ + (size_t)b * HW4_ + i4] = msk;
    }

    const float4* rfb = (const float4*)values + ((size_t)(B_ + b) * C_ + c0) * HW4_ + i4;
    const size_t tstride = (size_t)B_ * C_ * HW4_;

    float4 acc0 = make_float4(0.f, 0.f, 0.f, 0.f);
    float4 acc1 = acc0, acc2 = acc0, acc3 = acc0;
#pragma unroll
    for (int t = 0; t < T_; t++) {
        if (live & (1u << t)) {
            float4 w4 = cm[t];
            float4 r0 = __ldcs(rfb + t * tstride + 0 * HW4_);
            float4 r1 = __ldcs(rfb + t * tstride + 1 * HW4_);
            float4 r2 = __ldcs(rfb + t * tstride + 2 * HW4_);
            float4 r3 = __ldcs(rfb + t * tstride + 3 * HW4_);
            acc0.x += r0.x * w4.x; acc0.y += r0.y * w4.y; acc0.z += r0.z * w4.z; acc0.w += r0.w * w4.w;
            acc1.x += r1.x * w4.x; acc1.y += r1.y * w4.y; acc1.z += r1.z * w4.z; acc1.w += r1.w * w4.w;
            acc2.x += r2.x * w4.x; acc2.y += r2.y * w4.y; acc2.z += r2.z * w4.z; acc2.w += r2.w * w4.w;
            acc3.x += r3.x * w4.x; acc3.y += r3.y * w4.y; acc3.z += r3.z * w4.z; acc3.w += r3.w * w4.w;
        }
    }

    float4* outp = (float4*)d_out + ((size_t)b * 257 + 128 + c0) * HW4_ + i4;
    outp[0 * HW4_] = acc0;
    outp[1 * HW4_] = acc1;
    outp[2 * HW4_] = acc2;
    outp[3 * HW4_] = acc3;
}

// ---------------------------------------------------------------------------
extern "C" void kernel_launch(void* const* d_in, const int* in_sizes, int n_in,
                              void* d_out, int out_size) {
    const float* values = (const float*)d_in[0];   // (9,4,128,96,96)
    const float* tvmap  = (const float*)d_in[1];   // (4,1,384,384)
    const float* rvmaps = (const float*)d_in[2];   // (8,4,1,384,384)
    float* out = (float*)d_out;

    resize_kernel<<<(NMAP * HW_ + 255) / 256, 256>>>(tvmap, rvmaps);

    dim3 g1(18, 16, B_);
    pass1_kernel<<<g1, 128>>>(values, out);

    finalize_kernel<<<1, 256>>>(out);

    dim3 g2(9, 32, B_);
    pass2_kernel<<<g2, 256>>>(values, out);
}

// round 7
// speedup vs baseline: 1.1911x; 1.1911x over previous
#include <cuda_runtime.h>

#define T_ 8
#define B_ 4
#define C_ 128
#define HW_ 9216      // 96*96
#define HW4_ 2304     // HW_/4
#define NMAP 36       // T*B + B maps to resize
#define NTB 32        // T*B
#define NP1 288       // pass1 partials per tb: 18 px-tiles * 16 c-chunks
#define NPV 18        // vsum partials per tb

// scratch (static __device__ — no allocation)
__device__ float g_tv[B_ * HW_];
__device__ float g_rv[NTB * HW_];
__device__ float g_pgs[NTB * NP1];
__device__ float g_pvs[NTB * NPV];
__device__ float g_E[NTB];     // exp(gs)

// ---------------------------------------------------------------------------
// 1) antialiased (jax-style) 384->96 resize + threshold > 0.5
// ---------------------------------------------------------------------------
__global__ void resize_kernel(const float* __restrict__ tvmap,
                              const float* __restrict__ rvmaps) {
    int idx = blockIdx.x * blockDim.x + threadIdx.x;
    if (idx >= NMAP * HW_) return;
    int m = idx / HW_;
    int p = idx - m * HW_;
    int oy = p / 96, ox = p - oy * 96;

    const float* src = (m < B_) ? (tvmap + (size_t)m * 147456)
                                : (rvmaps + (size_t)(m - B_) * 147456);

    const float wtab[8] = {1.f, 3.f, 5.f, 7.f, 7.f, 5.f, 3.f, 1.f};
    int iy0 = 4 * oy - 2, ix0 = 4 * ox - 2;

    float wx[8];
    float wxs = 0.f;
#pragma unroll
    for (int k = 0; k < 8; k++) {
        int ix = ix0 + k;
        wx[k] = (ix >= 0 && ix < 384) ? wtab[k] : 0.f;
        wxs += wx[k];
    }

    float acc = 0.f, wys = 0.f;
#pragma unroll
    for (int ky = 0; ky < 8; ky++) {
        int iy = iy0 + ky;
        if (iy < 0 || iy >= 384) continue;
        wys += wtab[ky];
        const float* row = src + iy * 384;
        float ra = 0.f;
#pragma unroll
        for (int kx = 0; kx < 8; kx++) {
            if (wx[kx] != 0.f) ra += wx[kx] * row[ix0 + kx];
        }
        acc += wtab[ky] * ra;
    }
    float val = acc / (wys * wxs);
    float bin = (val > 0.5f) ? 1.f : 0.f;
    if (m < B_) g_tv[m * HW_ + p] = bin;
    else        g_rv[(m - B_) * HW_ + p] = bin;
}

// ---------------------------------------------------------------------------
// 2) masked correlation partials, t split in two halves of 4 (fewer regs).
//    grid = (18 px-tiles, 16 c-chunks of 8, 8 = b*2+thalf), 128 thr
// ---------------------------------------------------------------------------
__global__ void __launch_bounds__(128) pass1_kernel(const float* __restrict__ values,
                                                    float* __restrict__ d_out) {
    int bz = blockIdx.z;
    int b = bz >> 1;
    int th = bz & 1;            // t range [4*th, 4*th+4)
    int chunk = blockIdx.y;
    int c0 = chunk * 8;
    int i4 = blockIdx.x * 128 + threadIdx.x;   // 0..2303

    const float4* tf = (const float4*)values + ((size_t)b * C_ + c0) * HW4_ + i4;
    const float4* rf = (const float4*)values +
                       ((size_t)(B_ + (th * 4) * B_ + b) * C_ + c0) * HW4_ + i4;
    float4* outp = (float4*)d_out + ((size_t)b * 257 + c0) * HW4_ + i4;
    const size_t tstride = (size_t)B_ * C_ * HW4_;

    float4 acc[4];
#pragma unroll
    for (int t = 0; t < 4; t++) acc[t] = make_float4(0.f, 0.f, 0.f, 0.f);

#pragma unroll 2
    for (int c = 0; c < 8; c++) {
        float4 a = __ldg(tf + c * HW4_);
        if (th == 0) outp[c * HW4_] = a;   // t_feat -> out (written once)
#pragma unroll
        for (int t = 0; t < 4; t++) {
            float4 r = __ldcs(rf + t * tstride + c * HW4_);
            acc[t].x += a.x * r.x; acc[t].y += a.y * r.y;
            acc[t].z += a.z * r.z; acc[t].w += a.w * r.w;
        }
    }

    float4 tv = ((const float4*)g_tv)[b * HW4_ + i4];
    float lg[4], lv[4];
#pragma unroll
    for (int t = 0; t < 4; t++) {
        float4 rv = __ldg((const float4*)g_rv + ((th * 4 + t) * B_ + b) * HW4_ + i4);
        float m0 = tv.x * rv.x, m1 = tv.y * rv.y, m2 = tv.z * rv.z, m3 = tv.w * rv.w;
        lg[t] = acc[t].x * m0 + acc[t].y * m1 + acc[t].z * m2 + acc[t].w * m3;
        lv[t] = m0 + m1 + m2 + m3;
    }

#pragma unroll
    for (int o = 16; o > 0; o >>= 1) {
#pragma unroll
        for (int t = 0; t < 4; t++)
            lg[t] += __shfl_down_sync(0xffffffffu, lg[t], o);
    }
    if (chunk == 0) {
#pragma unroll
        for (int o = 16; o > 0; o >>= 1) {
#pragma unroll
            for (int t = 0; t < 4; t++)
                lv[t] += __shfl_down_sync(0xffffffffu, lv[t], o);
        }
    }

    __shared__ float sg[4][4], sv[4][4];
    int lane = threadIdx.x & 31, w = threadIdx.x >> 5;
    if (lane == 0) {
#pragma unroll
        for (int t = 0; t < 4; t++) { sg[w][t] = lg[t]; sv[w][t] = lv[t]; }
    }
    __syncthreads();
    if (threadIdx.x < 4) {
        int t = threadIdx.x;
        float a = 0.f, v = 0.f;
#pragma unroll
        for (int i = 0; i < 4; i++) { a += sg[i][t]; v += sv[i][t]; }
        int tb = (th * 4 + t) * B_ + b;
        g_pgs[tb * NP1 + blockIdx.x * 16 + chunk] = a;
        if (chunk == 0) g_pvs[tb * NPV + blockIdx.x] = v;
    }
}

// ---------------------------------------------------------------------------
// 3) finalize gs: reduce partials, write gs output, precompute E = exp(gs)
// ---------------------------------------------------------------------------
__global__ void __launch_bounds__(256) finalize_kernel(float* __restrict__ d_out) {
    int tb = threadIdx.x >> 3;
    int j = threadIdx.x & 7;
    float gsum = 0.f;
#pragma unroll
    for (int k = 0; k < NP1 / 8; k++) gsum += g_pgs[tb * NP1 + j + 8 * k];
#pragma unroll
    for (int o = 4; o > 0; o >>= 1)
        gsum += __shfl_down_sync(0xffffffffu, gsum, o, 8);
    if (j == 0) {
        float vsum = 0.f;
#pragma unroll
        for (int i = 0; i < NPV; i++) vsum += g_pvs[tb * NPV + i];
        float g = (vsum < 1e-4f) ? 0.f : (gsum / vsum) * (1.f / 128.f);
        g_E[tb] = expf(g);
        d_out[(size_t)B_ * 257 * HW_ + (size_t)B_ * HW_ + tb] = g;
    }
}

// ---------------------------------------------------------------------------
// 4) fused match + aggregate: acc = sum_t rv[t]*E[t]*rf[t]; out = acc / ms
//    (softmax max-shift cancels exactly; normalization commutes with c-sum)
//    grid = (9 px-tiles, 32 c-chunks of 4, 4 b)
// ---------------------------------------------------------------------------
__global__ void __launch_bounds__(256) pass2_kernel(const float* __restrict__ values,
                                                    float* __restrict__ d_out) {
    int i4 = blockIdx.x * 256 + threadIdx.x;   // 0..2303
    int c0 = blockIdx.y * 4;
    int b = blockIdx.z;

    __shared__ float sE[T_];
    if (threadIdx.x < T_) sE[threadIdx.x] = g_E[threadIdx.x * B_ + b];
    __syncthreads();

    const float4* rvp = (const float4*)g_rv + (size_t)b * HW4_ + i4;
    const float4* rfb = (const float4*)values + ((size_t)(B_ + b) * C_ + c0) * HW4_ + i4;
    const size_t tstride = (size_t)B_ * C_ * HW4_;
    const size_t rvstride = (size_t)B_ * HW4_;

    float4 ms = make_float4(0.f, 0.f, 0.f, 0.f);
    float4 acc0 = make_float4(0.f, 0.f, 0.f, 0.f);
    float4 acc1 = acc0, acc2 = acc0, acc3 = acc0;

#pragma unroll
    for (int t = 0; t < T_; t++) {
        float4 rv = __ldg(rvp + t * rvstride);
        float e = sE[t];
        float4 w4 = make_float4(rv.x * e, rv.y * e, rv.z * e, rv.w * e);
        ms.x += w4.x; ms.y += w4.y; ms.z += w4.z; ms.w += w4.w;
        float4 r0 = __ldcs(rfb + t * tstride + 0 * HW4_);
        float4 r1 = __ldcs(rfb + t * tstride + 1 * HW4_);
        float4 r2 = __ldcs(rfb + t * tstride + 2 * HW4_);
        float4 r3 = __ldcs(rfb + t * tstride + 3 * HW4_);
        acc0.x += r0.x * w4.x; acc0.y += r0.y * w4.y; acc0.z += r0.z * w4.z; acc0.w += r0.w * w4.w;
        acc1.x += r1.x * w4.x; acc1.y += r1.y * w4.y; acc1.z += r1.z * w4.z; acc1.w += r1.w * w4.w;
        acc2.x += r2.x * w4.x; acc2.y += r2.y * w4.y; acc2.z += r2.z * w4.z; acc2.w += r2.w * w4.w;
        acc3.x += r3.x * w4.x; acc3.y += r3.y * w4.y; acc3.z += r3.z * w4.z; acc3.w += r3.w * w4.w;
    }

    float4 inv;
    inv.x = 1.f / (ms.x + ((ms.x < 1e-4f) ? 1.f : 0.f));
    inv.y = 1.f / (ms.y + ((ms.y < 1e-4f) ? 1.f : 0.f));
    inv.z = 1.f / (ms.z + ((ms.z < 1e-4f) ? 1.f : 0.f));
    inv.w = 1.f / (ms.w + ((ms.w < 1e-4f) ? 1.f : 0.f));

    if (blockIdx.y == 0) {   // c_mask = 1 - ms/msd, written once per pixel
        float4 msk = make_float4(1.f - ms.x * inv.x, 1.f - ms.y * inv.y,
                                 1.f - ms.z * inv.z, 1.f - ms.w * inv.w);
        float4* op = (float4*)d_out;
        op[((size_t)b * 257 + 256) * HW4_ + i4] = msk;
        op[(size_t)B_ * 257 * HW4_ + (size_t)b * HW4_ + i4] = msk;
    }

    acc0.x *= inv.x; acc0.y *= inv.y; acc0.z *= inv.z; acc0.w *= inv.w;
    acc1.x *= inv.x; acc1.y *= inv.y; acc1.z *= inv.z; acc1.w *= inv.w;
    acc2.x *= inv.x; acc2.y *= inv.y; acc2.z *= inv.z; acc2.w *= inv.w;
    acc3.x *= inv.x; acc3.y *= inv.y; acc3.z *= inv.z; acc3.w *= inv.w;

    float4* outp = (float4*)d_out + ((size_t)b * 257 + 128 + c0) * HW4_ + i4;
    outp[0 * HW4_] = acc0;
    outp[1 * HW4_] = acc1;
    outp[2 * HW4_] = acc2;
    outp[3 * HW4_] = acc3;
}

// ---------------------------------------------------------------------------
extern "C" void kernel_launch(void* const* d_in, const int* in_sizes, int n_in,
                              void* d_out, int out_size) {
    const float* values = (const float*)d_in[0];   // (9,4,128,96,96)
    const float* tvmap  = (const float*)d_in[1];   // (4,1,384,384)
    const float* rvmaps = (const float*)d_in[2];   // (8,4,1,384,384)
    float* out = (float*)d_out;

    resize_kernel<<<(NMAP * HW_ + 255) / 256, 256>>>(tvmap, rvmaps);

    dim3 g1(18, 16, 8);
    pass1_kernel<<<g1, 128>>>(values, out);

    finalize_kernel<<<1, 256>>>(out);

    dim3 g2(9, 32, B_);
    pass2_kernel<<<g2, 256>>>(values, out);
}

// round 8
// speedup vs baseline: 1.2423x; 1.0430x over previous
#include <cuda_runtime.h>

#define T_ 8
#define B_ 4
#define C_ 128
#define HW_ 9216      // 96*96
#define HW4_ 2304     // HW_/4
#define NMAP 36       // T*B + B maps to resize
#define NTB 32        // T*B
#define NP1 288       // pass1 partials per tb: 18 px-tiles * 16 c-chunks
#define NPV 18        // vsum partials per tb

// scratch (static __device__ — no allocation)
__device__ float g_tv[B_ * HW_];
__device__ float g_rv[NTB * HW_];
__device__ float g_pgs[NTB * NP1];
__device__ float g_pvs[NTB * NPV];
__device__ float g_E[NTB];     // exp(gs)

// ---------------------------------------------------------------------------
// 1) antialiased (jax-style) 384->96 resize + threshold > 0.5
// ---------------------------------------------------------------------------
__global__ void resize_kernel(const float* __restrict__ tvmap,
                              const float* __restrict__ rvmaps) {
    int idx = blockIdx.x * blockDim.x + threadIdx.x;
    if (idx >= NMAP * HW_) return;
    int m = idx / HW_;
    int p = idx - m * HW_;
    int oy = p / 96, ox = p - oy * 96;

    const float* src = (m < B_) ? (tvmap + (size_t)m * 147456)
                                : (rvmaps + (size_t)(m - B_) * 147456);

    const float wtab[8] = {1.f, 3.f, 5.f, 7.f, 7.f, 5.f, 3.f, 1.f};
    int iy0 = 4 * oy - 2, ix0 = 4 * ox - 2;

    float wx[8];
    float wxs = 0.f;
#pragma unroll
    for (int k = 0; k < 8; k++) {
        int ix = ix0 + k;
        wx[k] = (ix >= 0 && ix < 384) ? wtab[k] : 0.f;
        wxs += wx[k];
    }

    float acc = 0.f, wys = 0.f;
#pragma unroll
    for (int ky = 0; ky < 8; ky++) {
        int iy = iy0 + ky;
        if (iy < 0 || iy >= 384) continue;
        wys += wtab[ky];
        const float* row = src + iy * 384;
        float ra = 0.f;
#pragma unroll
        for (int kx = 0; kx < 8; kx++) {
            if (wx[kx] != 0.f) ra += wx[kx] * row[ix0 + kx];
        }
        acc += wtab[ky] * ra;
    }
    float val = acc / (wys * wxs);
    float bin = (val > 0.5f) ? 1.f : 0.f;
    if (m < B_) g_tv[m * HW_ + p] = bin;
    else        g_rv[(m - B_) * HW_ + p] = bin;
}

// ---------------------------------------------------------------------------
// 2) masked correlation partials, t split in two halves of 4.
//    rf loads use DEFAULT caching so the stream tail stays resident in L2
//    for pass2 (which consumes in reverse order).
//    grid = (18 px-tiles, 16 c-chunks of 8, 8 = b*2+thalf), 128 thr
// ---------------------------------------------------------------------------
__global__ void __launch_bounds__(128) pass1_kernel(const float* __restrict__ values,
                                                    float* __restrict__ d_out) {
    int bz = blockIdx.z;
    int b = bz >> 1;
    int th = bz & 1;            // t range [4*th, 4*th+4)
    int chunk = blockIdx.y;
    int c0 = chunk * 8;
    int i4 = blockIdx.x * 128 + threadIdx.x;   // 0..2303

    const float4* tf = (const float4*)values + ((size_t)b * C_ + c0) * HW4_ + i4;
    const float4* rf = (const float4*)values +
                       ((size_t)(B_ + (th * 4) * B_ + b) * C_ + c0) * HW4_ + i4;
    float4* outp = (float4*)d_out + ((size_t)b * 257 + c0) * HW4_ + i4;
    const size_t tstride = (size_t)B_ * C_ * HW4_;

    float4 acc[4];
#pragma unroll
    for (int t = 0; t < 4; t++) acc[t] = make_float4(0.f, 0.f, 0.f, 0.f);

#pragma unroll 4
    for (int c = 0; c < 8; c++) {
        float4 a = __ldg(tf + c * HW4_);
        if (th == 0) outp[c * HW4_] = a;   // t_feat -> out (written once)
#pragma unroll
        for (int t = 0; t < 4; t++) {
            float4 r = rf[t * tstride + c * HW4_];   // default policy: fills L2
            acc[t].x += a.x * r.x; acc[t].y += a.y * r.y;
            acc[t].z += a.z * r.z; acc[t].w += a.w * r.w;
        }
    }

    float4 tv = ((const float4*)g_tv)[b * HW4_ + i4];
    float lg[4], lv[4];
#pragma unroll
    for (int t = 0; t < 4; t++) {
        float4 rv = __ldg((const float4*)g_rv + ((th * 4 + t) * B_ + b) * HW4_ + i4);
        float m0 = tv.x * rv.x, m1 = tv.y * rv.y, m2 = tv.z * rv.z, m3 = tv.w * rv.w;
        lg[t] = acc[t].x * m0 + acc[t].y * m1 + acc[t].z * m2 + acc[t].w * m3;
        lv[t] = m0 + m1 + m2 + m3;
    }

#pragma unroll
    for (int o = 16; o > 0; o >>= 1) {
#pragma unroll
        for (int t = 0; t < 4; t++)
            lg[t] += __shfl_down_sync(0xffffffffu, lg[t], o);
    }
    if (chunk == 0) {
#pragma unroll
        for (int o = 16; o > 0; o >>= 1) {
#pragma unroll
            for (int t = 0; t < 4; t++)
                lv[t] += __shfl_down_sync(0xffffffffu, lv[t], o);
        }
    }

    __shared__ float sg[4][4], sv[4][4];
    int lane = threadIdx.x & 31, w = threadIdx.x >> 5;
    if (lane == 0) {
#pragma unroll
        for (int t = 0; t < 4; t++) { sg[w][t] = lg[t]; sv[w][t] = lv[t]; }
    }
    __syncthreads();
    if (threadIdx.x < 4) {
        int t = threadIdx.x;
        float a = 0.f, v = 0.f;
#pragma unroll
        for (int i = 0; i < 4; i++) { a += sg[i][t]; v += sv[i][t]; }
        int tb = (th * 4 + t) * B_ + b;
        g_pgs[tb * NP1 + blockIdx.x * 16 + chunk] = a;
        if (chunk == 0) g_pvs[tb * NPV + blockIdx.x] = v;
    }
}

// ---------------------------------------------------------------------------
// 3) finalize gs: reduce partials, write gs output, precompute E = exp(gs)
// ---------------------------------------------------------------------------
__global__ void __launch_bounds__(256) finalize_kernel(float* __restrict__ d_out) {
    int tb = threadIdx.x >> 3;
    int j = threadIdx.x & 7;
    float gsum = 0.f;
#pragma unroll
    for (int k = 0; k < NP1 / 8; k++) gsum += g_pgs[tb * NP1 + j + 8 * k];
#pragma unroll
    for (int o = 4; o > 0; o >>= 1)
        gsum += __shfl_down_sync(0xffffffffu, gsum, o, 8);
    if (j == 0) {
        float vsum = 0.f;
#pragma unroll
        for (int i = 0; i < NPV; i++) vsum += g_pvs[tb * NPV + i];
        float g = (vsum < 1e-4f) ? 0.f : (gsum / vsum) * (1.f / 128.f);
        g_E[tb] = expf(g);
        d_out[(size_t)B_ * 257 * HW_ + (size_t)B_ * HW_ + tb] = g;
    }
}

// ---------------------------------------------------------------------------
// 4) fused match + aggregate, consuming r_feats in REVERSE of pass1's stream
//    order to hit the L2-resident tail.  grid = (9 px-tiles, 32 c-chunks, 4 b)
// ---------------------------------------------------------------------------
__global__ void __launch_bounds__(256) pass2_kernel(const float* __restrict__ values,
                                                    float* __restrict__ d_out) {
    int i4 = (8 - blockIdx.x) * 256 + threadIdx.x;  // reversed px tiles
    int c0 = (31 - blockIdx.y) * 4;                 // reversed c-chunks
    int b = 3 - blockIdx.z;                         // reversed batch

    __shared__ float sE[T_];
    if (threadIdx.x < T_) sE[threadIdx.x] = g_E[threadIdx.x * B_ + b];
    __syncthreads();

    const float4* rvp = (const float4*)g_rv + (size_t)b * HW4_ + i4;
    const float4* rfb = (const float4*)values + ((size_t)(B_ + b) * C_ + c0) * HW4_ + i4;
    const size_t tstride = (size_t)B_ * C_ * HW4_;
    const size_t rvstride = (size_t)B_ * HW4_;

    float4 ms = make_float4(0.f, 0.f, 0.f, 0.f);
    float4 acc0 = make_float4(0.f, 0.f, 0.f, 0.f);
    float4 acc1 = acc0, acc2 = acc0, acc3 = acc0;

#pragma unroll
    for (int t = T_ - 1; t >= 0; t--) {   // reversed t: hottest slabs first
        float4 rv = __ldg(rvp + t * rvstride);
        float e = sE[t];
        float4 w4 = make_float4(rv.x * e, rv.y * e, rv.z * e, rv.w * e);
        ms.x += w4.x; ms.y += w4.y; ms.z += w4.z; ms.w += w4.w;
        float4 r0 = __ldcs(rfb + t * tstride + 0 * HW4_);
        float4 r1 = __ldcs(rfb + t * tstride + 1 * HW4_);
        float4 r2 = __ldcs(rfb + t * tstride + 2 * HW4_);
        float4 r3 = __ldcs(rfb + t * tstride + 3 * HW4_);
        acc0.x += r0.x * w4.x; acc0.y += r0.y * w4.y; acc0.z += r0.z * w4.z; acc0.w += r0.w * w4.w;
        acc1.x += r1.x * w4.x; acc1.y += r1.y * w4.y; acc1.z += r1.z * w4.z; acc1.w += r1.w * w4.w;
        acc2.x += r2.x * w4.x; acc2.y += r2.y * w4.y; acc2.z += r2.z * w4.z; acc2.w += r2.w * w4.w;
        acc3.x += r3.x * w4.x; acc3.y += r3.y * w4.y; acc3.z += r3.z * w4.z; acc3.w += r3.w * w4.w;
    }

    float4 inv;
    inv.x = 1.f / (ms.x + ((ms.x < 1e-4f) ? 1.f : 0.f));
    inv.y = 1.f / (ms.y + ((ms.y < 1e-4f) ? 1.f : 0.f));
    inv.z = 1.f / (ms.z + ((ms.z < 1e-4f) ? 1.f : 0.f));
    inv.w = 1.f / (ms.w + ((ms.w < 1e-4f) ? 1.f : 0.f));

    if (blockIdx.y == 31) {  // c0==0 blocks: c_mask written once per pixel
        float4 msk = make_float4(1.f - ms.x * inv.x, 1.f - ms.y * inv.y,
                                 1.f - ms.z * inv.z, 1.f - ms.w * inv.w);
        float4* op = (float4*)d_out;
        op[((size_t)b * 257 + 256) * HW4_ + i4] = msk;
        op[(size_t)B_ * 257 * HW4_ + (size_t)b * HW4_ + i4] = msk;
    }

    acc0.x *= inv.x; acc0.y *= inv.y; acc0.z *= inv.z; acc0.w *= inv.w;
    acc1.x *= inv.x; acc1.y *= inv.y; acc1.z *= inv.z; acc1.w *= inv.w;
    acc2.x *= inv.x; acc2.y *= inv.y; acc2.z *= inv.z; acc2.w *= inv.w;
    acc3.x *= inv.x; acc3.y *= inv.y; acc3.z *= inv.z; acc3.w *= inv.w;

    float4* outp = (float4*)d_out + ((size_t)b * 257 + 128 + c0) * HW4_ + i4;
    outp[0 * HW4_] = acc0;
    outp[1 * HW4_] = acc1;
    outp[2 * HW4_] = acc2;
    outp[3 * HW4_] = acc3;
}

// ---------------------------------------------------------------------------
extern "C" void kernel_launch(void* const* d_in, const int* in_sizes, int n_in,
                              void* d_out, int out_size) {
    const float* values = (const float*)d_in[0];   // (9,4,128,96,96)
    const float* tvmap  = (const float*)d_in[1];   // (4,1,384,384)
    const float* rvmaps = (const float*)d_in[2];   // (8,4,1,384,384)
    float* out = (float*)d_out;

    resize_kernel<<<(NMAP * HW_ + 255) / 256, 256>>>(tvmap, rvmaps);

    dim3 g1(18, 16, 8);
    pass1_kernel<<<g1, 128>>>(values, out);

    finalize_kernel<<<1, 256>>>(out);

    dim3 g2(9, 32, B_);
    pass2_kernel<<<g2, 256>>>(values, out);
}

// round 9
// speedup vs baseline: 1.2547x; 1.0100x over previous
#include <cuda_runtime.h>

#define T_ 8
#define B_ 4
#define C_ 128
#define HW_ 9216      // 96*96
#define HW4_ 2304     // HW_/4
#define NMAP 36       // T*B + B maps to resize
#define NTB 32        // T*B
#define GRID_ 576     // 9 px-tiles * 16 c-chunks * 4 b
#define NSLOT 144     // partial slots per tb: 9 px * 16 c-chunks
#define NPV 9         // vsum partials per tb

// scratch (static __device__ — no allocation)
__device__ float g_tv[B_ * HW_];
__device__ float g_rv[NTB * HW_];
__device__ float g_pgs[NTB * NSLOT];
__device__ float g_pvs[NTB * NPV];
__device__ unsigned int g_bar = 0;   // cumulative ticket barrier (never reset)

// ---------------------------------------------------------------------------
// 1) antialiased (jax-style) 384->96 resize + threshold > 0.5
// ---------------------------------------------------------------------------
__global__ void resize_kernel(const float* __restrict__ tvmap,
                              const float* __restrict__ rvmaps) {
    int idx = blockIdx.x * blockDim.x + threadIdx.x;
    if (idx >= NMAP * HW_) return;
    int m = idx / HW_;
    int p = idx - m * HW_;
    int oy = p / 96, ox = p - oy * 96;

    const float* src = (m < B_) ? (tvmap + (size_t)m * 147456)
                                : (rvmaps + (size_t)(m - B_) * 147456);

    const float wtab[8] = {1.f, 3.f, 5.f, 7.f, 7.f, 5.f, 3.f, 1.f};
    int iy0 = 4 * oy - 2, ix0 = 4 * ox - 2;

    float wx[8];
    float wxs = 0.f;
#pragma unroll
    for (int k = 0; k < 8; k++) {
        int ix = ix0 + k;
        wx[k] = (ix >= 0 && ix < 384) ? wtab[k] : 0.f;
        wxs += wx[k];
    }

    float acc = 0.f, wys = 0.f;
#pragma unroll
    for (int ky = 0; ky < 8; ky++) {
        int iy = iy0 + ky;
        if (iy < 0 || iy >= 384) continue;
        wys += wtab[ky];
        const float* row = src + iy * 384;
        float ra = 0.f;
#pragma unroll
        for (int kx = 0; kx < 8; kx++) {
            if (wx[kx] != 0.f) ra += wx[kx] * row[ix0 + kx];
        }
        acc += wtab[ky] * ra;
    }
    float val = acc / (wys * wxs);
    float bin = (val > 0.5f) ? 1.f : 0.f;
    if (m < B_) g_tv[m * HW_ + p] = bin;
    else        g_rv[(m - B_) * HW_ + p] = bin;
}

// ---------------------------------------------------------------------------
// 2) FUSED persistent kernel: phase A (gs partials + t_feat passthrough),
//    software grid barrier, phase B (gs finalize + match + aggregate).
//    grid = (9 px-tiles, 16 c-chunks of 8, 4 b) = 576 blocks of 256 thr,
//    __launch_bounds__(256,4) guarantees 4 blocks/SM -> all co-resident.
// ---------------------------------------------------------------------------
__global__ void __launch_bounds__(256, 4) fused_kernel(const float* __restrict__ values,
                                                       float* __restrict__ d_out) {
    int px = blockIdx.x;
    int chunk = blockIdx.y;
    int b = blockIdx.z;
    int c0 = chunk * 8;
    int tid = threadIdx.x;
    int i4 = px * 256 + tid;          // 0..2303

    const float4* vals4 = (const float4*)values;
    const float4* tf = vals4 + ((size_t)b * C_ + c0) * HW4_ + i4;
    float4* outp = (float4*)d_out + ((size_t)b * 257 + c0) * HW4_ + i4;
    const size_t tstride = (size_t)B_ * C_ * HW4_;

    float4 tv = ((const float4*)g_tv)[b * HW4_ + i4];

    __shared__ float sg[8][4], sv[8][4];
    int lane = tid & 31, w = tid >> 5;

    // ================= phase A: masked correlation partials =================
#pragma unroll
    for (int h = 0; h < 2; h++) {     // t halves: [0,4) and [4,8)
        const float4* rf = vals4 + ((size_t)(B_ + h * 4 * B_ + b) * C_ + c0) * HW4_ + i4;

        float4 acc[4];
#pragma unroll
        for (int t = 0; t < 4; t++) acc[t] = make_float4(0.f, 0.f, 0.f, 0.f);

#pragma unroll
        for (int c = 0; c < 8; c++) {
            float4 a = __ldg(tf + c * HW4_);             // L1-resident on 2nd half
            if (h == 0) __stcs(&outp[c * HW4_], a);      // t_feat passthrough
#pragma unroll
            for (int t = 0; t < 4; t++) {
                float4 r = __ldcg(rf + t * tstride + c * HW4_);  // L2 fill, skip L1
                acc[t].x += a.x * r.x; acc[t].y += a.y * r.y;
                acc[t].z += a.z * r.z; acc[t].w += a.w * r.w;
            }
        }

        float lg[4], lv[4];
#pragma unroll
        for (int t = 0; t < 4; t++) {
            float4 rv = __ldg((const float4*)g_rv + ((h * 4 + t) * B_ + b) * HW4_ + i4);
            float m0 = tv.x * rv.x, m1 = tv.y * rv.y, m2 = tv.z * rv.z, m3 = tv.w * rv.w;
            lg[t] = acc[t].x * m0 + acc[t].y * m1 + acc[t].z * m2 + acc[t].w * m3;
            lv[t] = m0 + m1 + m2 + m3;
        }
#pragma unroll
        for (int o = 16; o > 0; o >>= 1) {
#pragma unroll
            for (int t = 0; t < 4; t++) {
                lg[t] += __shfl_down_sync(0xffffffffu, lg[t], o);
                lv[t] += __shfl_down_sync(0xffffffffu, lv[t], o);
            }
        }
        if (lane == 0) {
#pragma unroll
            for (int t = 0; t < 4; t++) { sg[w][t] = lg[t]; sv[w][t] = lv[t]; }
        }
        __syncthreads();
        if (tid < 4) {
            int t = h * 4 + tid;
            int tb = t * B_ + b;
            float a = 0.f, v = 0.f;
#pragma unroll
            for (int i = 0; i < 8; i++) { a += sg[i][tid]; v += sv[i][tid]; }
            g_pgs[tb * NSLOT + px * 16 + chunk] = a;
            if (chunk == 0) g_pvs[tb * NPV + px] = v;
        }
        __syncthreads();
    }

    // ===================== software grid barrier =====================
    __threadfence();
    if (tid == 0) {
        unsigned int ticket = atomicAdd(&g_bar, 1u);
        unsigned int target = (ticket / GRID_ + 1u) * GRID_;
        while (*((volatile unsigned int*)&g_bar) < target) __nanosleep(64);
    }
    __syncthreads();
    __threadfence();

    // ============== phase B: gs finalize + match + aggregate ==============
    __shared__ float sE[T_];
    if (tid < 128) {
        int t = tid >> 4, j = tid & 15;
        int tb = t * B_ + b;
        float s = 0.f;
#pragma unroll
        for (int k = 0; k < 9; k++) s += g_pgs[tb * NSLOT + k * 16 + j];
#pragma unroll
        for (int o = 8; o > 0; o >>= 1)
            s += __shfl_down_sync(0xffffffffu, s, o, 16);
        if (j == 0) {
            float vs = 0.f;
#pragma unroll
            for (int k = 0; k < NPV; k++) vs += g_pvs[tb * NPV + k];
            float g = (vs < 1e-4f) ? 0.f : (s / vs) * (1.f / 128.f);
            sE[t] = expf(g);
            if (px == 0 && chunk == 0)
                d_out[(size_t)B_ * 257 * HW_ + (size_t)B_ * HW_ + tb] = g;
        }
    }
    __syncthreads();

    const float4* rvp = (const float4*)g_rv + (size_t)b * HW4_ + i4;
    const size_t rvstride = (size_t)B_ * HW4_;

    float4 ms = make_float4(0.f, 0.f, 0.f, 0.f);
    float4 inv;
#pragma unroll
    for (int grp = 0; grp < 2; grp++) {   // two 4-channel groups of this chunk
        int cc0 = c0 + grp * 4;
        const float4* rfb = vals4 + ((size_t)(B_ + b) * C_ + cc0) * HW4_ + i4;

        float4 acc0 = make_float4(0.f, 0.f, 0.f, 0.f);
        float4 acc1 = acc0, acc2 = acc0, acc3 = acc0;
#pragma unroll
        for (int t = 0; t < T_; t++) {
            float4 rv = __ldg(rvp + t * rvstride);
            float e = sE[t];
            float4 w4 = make_float4(rv.x * e, rv.y * e, rv.z * e, rv.w * e);
            if (grp == 0) { ms.x += w4.x; ms.y += w4.y; ms.z += w4.z; ms.w += w4.w; }
            float4 r0 = __ldcs(rfb + t * tstride + 0 * HW4_);
            float4 r1 = __ldcs(rfb + t * tstride + 1 * HW4_);
            float4 r2 = __ldcs(rfb + t * tstride + 2 * HW4_);
            float4 r3 = __ldcs(rfb + t * tstride + 3 * HW4_);
            acc0.x += r0.x * w4.x; acc0.y += r0.y * w4.y; acc0.z += r0.z * w4.z; acc0.w += r0.w * w4.w;
            acc1.x += r1.x * w4.x; acc1.y += r1.y * w4.y; acc1.z += r1.z * w4.z; acc1.w += r1.w * w4.w;
            acc2.x += r2.x * w4.x; acc2.y += r2.y * w4.y; acc2.z += r2.z * w4.z; acc2.w += r2.w * w4.w;
            acc3.x += r3.x * w4.x; acc3.y += r3.y * w4.y; acc3.z += r3.z * w4.z; acc3.w += r3.w * w4.w;
        }

        if (grp == 0) {
            inv.x = 1.f / (ms.x + ((ms.x < 1e-4f) ? 1.f : 0.f));
            inv.y = 1.f / (ms.y + ((ms.y < 1e-4f) ? 1.f : 0.f));
            inv.z = 1.f / (ms.z + ((ms.z < 1e-4f) ? 1.f : 0.f));
            inv.w = 1.f / (ms.w + ((ms.w < 1e-4f) ? 1.f : 0.f));
            if (chunk == 0) {   // c_mask written once per pixel
                float4 msk = make_float4(1.f - ms.x * inv.x, 1.f - ms.y * inv.y,
                                         1.f - ms.z * inv.z, 1.f - ms.w * inv.w);
                float4* op = (float4*)d_out;
                __stcs(&op[((size_t)b * 257 + 256) * HW4_ + i4], msk);
                __stcs(&op[(size_t)B_ * 257 * HW4_ + (size_t)b * HW4_ + i4], msk);
            }
        }

        acc0.x *= inv.x; acc0.y *= inv.y; acc0.z *= inv.z; acc0.w *= inv.w;
        acc1.x *= inv.x; acc1.y *= inv.y; acc1.z *= inv.z; acc1.w *= inv.w;
        acc2.x *= inv.x; acc2.y *= inv.y; acc2.z *= inv.z; acc2.w *= inv.w;
        acc3.x *= inv.x; acc3.y *= inv.y; acc3.z *= inv.z; acc3.w *= inv.w;

        float4* outc = (float4*)d_out + ((size_t)b * 257 + 128 + cc0) * HW4_ + i4;
        __stcs(&outc[0 * HW4_], acc0);
        __stcs(&outc[1 * HW4_], acc1);
        __stcs(&outc[2 * HW4_], acc2);
        __stcs(&outc[3 * HW4_], acc3);
    }
}

// ---------------------------------------------------------------------------
extern "C" void kernel_launch(void* const* d_in, const int* in_sizes, int n_in,
                              void* d_out, int out_size) {
    const float* values = (const float*)d_in[0];   // (9,4,128,96,96)
    const float* tvmap  = (const float*)d_in[1];   // (4,1,384,384)
    const float* rvmaps = (const float*)d_in[2];   // (8,4,1,384,384)
    float* out = (float*)d_out;

    resize_kernel<<<(NMAP * HW_ + 255) / 256, 256>>>(tvmap, rvmaps);

    dim3 gf(9, 16, B_);
    fused_kernel<<<gf, 256>>>(values, out);
}